// round 1
// baseline (speedup 1.0000x reference)
#include <cuda_runtime.h>

// Conv2D: X [B=64, 1024, 1024] fp32, W [7,7] fp32, stride 1, pad 3.
// Output [64, 1024, 1024] fp32.
//
// Tiling: block = 32x8 threads; each thread computes TX=2 x TY=4 outputs
// -> 64x32 output tile per block. Input tile (64+6) x (32+6) in smem.

#define IMG_H 1024
#define IMG_W 1024
#define KS 7
#define PAD 3

#define BX 32      // threads x
#define BY 8       // threads y
#define TX 2       // outputs per thread x
#define TY 4       // outputs per thread y
#define TILE_W (BX * TX)          // 64
#define TILE_H (BY * TY)          // 32
#define IN_W (TILE_W + KS - 1)    // 70
#define IN_H (TILE_H + KS - 1)    // 38
#define SMEM_PITCH 72             // padded pitch (floats), keeps 8B alignment

__global__ __launch_bounds__(BX * BY, 3)
void conv7x7_kernel(const float* __restrict__ X,
                    const float* __restrict__ W,
                    float* __restrict__ out) {
    __shared__ float s_tile[IN_H * SMEM_PITCH];
    __shared__ float s_w[KS * KS];

    const int tid = threadIdx.y * BX + threadIdx.x;
    const int tileX0 = blockIdx.x * TILE_W;
    const int tileY0 = blockIdx.y * TILE_H;
    const int b = blockIdx.z;

    const float* Xb = X + (size_t)b * IMG_H * IMG_W;

    // Load weights into smem
    if (tid < KS * KS) s_w[tid] = W[tid];

    // Load input tile (with zero padding at image borders)
    const int gx0 = tileX0 - PAD;
    const int gy0 = tileY0 - PAD;
    for (int i = tid; i < IN_H * IN_W; i += BX * BY) {
        int r = i / IN_W;
        int c = i - r * IN_W;
        int gy = gy0 + r;
        int gx = gx0 + c;
        float v = 0.0f;
        if (gy >= 0 && gy < IMG_H && gx >= 0 && gx < IMG_W)
            v = __ldg(&Xb[(size_t)gy * IMG_W + gx]);
        s_tile[r * SMEM_PITCH + c] = v;
    }
    __syncthreads();

    // Copy weights to registers (uniform broadcast loads)
    float w[KS * KS];
#pragma unroll
    for (int i = 0; i < KS * KS; ++i) w[i] = s_w[i];

    const int lx = threadIdx.x * TX;     // local col of first output
    const int ly = threadIdx.y * TY;     // local row of first output

    float acc[TY][TX];
#pragma unroll
    for (int ry = 0; ry < TY; ++ry)
#pragma unroll
        for (int rx = 0; rx < TX; ++rx) acc[ry][rx] = 0.0f;

    // Slide over input rows; each input row ir feeds output rows
    // ry in [ir-6, ir] inter [0, TY-1] with ky = ir - ry.
#pragma unroll
    for (int ir = 0; ir < TY + KS - 1; ++ir) {
        float in[TX + KS - 1];
        const float* row = &s_tile[(ly + ir) * SMEM_PITCH + lx];
#pragma unroll
        for (int j = 0; j < TX + KS - 1; ++j) in[j] = row[j];

#pragma unroll
        for (int ry = 0; ry < TY; ++ry) {
            const int ky = ir - ry;
            if (ky >= 0 && ky < KS) {
#pragma unroll
                for (int kx = 0; kx < KS; ++kx) {
                    const float wk = w[ky * KS + kx];
                    acc[ry][0] = fmaf(in[kx], wk, acc[ry][0]);
                    acc[ry][1] = fmaf(in[kx + 1], wk, acc[ry][1]);
                }
            }
        }
    }

    // Store (coalesced float2 per row)
    float* outb = out + (size_t)b * IMG_H * IMG_W;
    const int ox = tileX0 + lx;
    const int oy = tileY0 + ly;
#pragma unroll
    for (int ry = 0; ry < TY; ++ry) {
        float2 v = make_float2(acc[ry][0], acc[ry][1]);
        *reinterpret_cast<float2*>(&outb[(size_t)(oy + ry) * IMG_W + ox]) = v;
    }
}

extern "C" void kernel_launch(void* const* d_in, const int* in_sizes, int n_in,
                              void* d_out, int out_size) {
    const float* X = (const float*)d_in[0];
    const float* W = (const float*)d_in[1];
    float* out = (float*)d_out;

    dim3 block(BX, BY);
    dim3 grid(IMG_W / TILE_W, IMG_H / TILE_H, 64);
    conv7x7_kernel<<<grid, block>>>(X, W, out);
}